// round 1
// baseline (speedup 1.0000x reference)
#include <cuda_runtime.h>
#include <math.h>

#define FATOL 1e-8f
#define FRTOL 1e-5f
#define EP3   0.0003f      /* 3 * EP, EP = 1e-4 */
#define EPMAX2 900.0f      /* EPMAX^2 */

#define MAX_L 2048
#define MAX_P 131072
#define MAX_F (MAX_L + MAX_P)
#define NB_MAIN 304
#define NT_MAIN 256
#define MAX_PPT 12         /* points per thread: 3*1024 / 256 */

__device__ int    g_pair_count;
__device__ double g_sum;
__device__ int2   g_pairs[MAX_P];
__device__ float4 g_frames4[MAX_F * 6];   /* per frame: Rp[9], Rt[9], c[3], pad[3] */
__device__ float  g_trot[MAX_L * 9];
__device__ float  g_ttran[MAX_L * 3];

/* ------------------------------------------------------------------ */
__global__ void init_kernel() {
    g_pair_count = 0;
    g_sum = 0.0;
}

/* ---------------- pair extraction (warp-aggregated atomics) -------- */
__global__ void pairs_kernel(const int* __restrict__ m, int L) {
    int i = blockIdx.x;
    int j = blockIdx.y * blockDim.x + threadIdx.x;
    bool pred = (j < L) && (j > i) && (m[(long)i * L + j] == 1);
    unsigned bal = __ballot_sync(0xffffffffu, pred);
    int cnt = __popc(bal);
    int lane = threadIdx.x & 31;
    int base = 0;
    if (lane == 0 && cnt) base = atomicAdd(&g_pair_count, cnt);
    base = __shfl_sync(0xffffffffu, base, 0);
    if (pred) {
        int r = base + __popc(bal & ((1u << lane) - 1u));
        if (r < MAX_P) g_pairs[r] = make_int2(i, j);
    }
}

/* ---------------- frame math helpers ------------------------------ */
__device__ __forceinline__ void write_record(int f, const float* Rp, const float* tp,
                                             const float* Rt, const float* tq) {
    float* o = ((float*)g_frames4) + (long)f * 24;
#pragma unroll
    for (int k = 0; k < 9; k++) o[k] = Rp[k];
#pragma unroll
    for (int k = 0; k < 9; k++) o[9 + k] = Rt[k];
#pragma unroll
    for (int e = 0; e < 3; e++) {
        float c = (Rt[3*e+0]*tq[0] + Rt[3*e+1]*tq[1] + Rt[3*e+2]*tq[2])
                - (Rp[3*e+0]*tp[0] + Rp[3*e+1]*tp[1] + Rp[3*e+2]*tp[2]);
        o[18 + e] = c;
    }
    o[21] = 0.f; o[22] = 0.f; o[23] = 0.f;
}

__device__ __forceinline__ void merge_frames_dev(
    const float* RA, const float* OA, const float* RB, const float* OB,
    float* R, float* O)
{
    bool close = (fabsf(OA[0]-OB[0]) <= FATOL + FRTOL*fabsf(OB[0]))
              && (fabsf(OA[1]-OB[1]) <= FATOL + FRTOL*fabsf(OB[1]))
              && (fabsf(OA[2]-OB[2]) <= FATOL + FRTOL*fabsf(OB[2]));
    float d0 = OB[0]-OA[0], d1 = OB[1]-OA[1], d2 = OB[2]-OA[2];
    float nd = sqrtf(d0*d0 + d1*d1 + d2*d2);
    float snd = (nd == 0.f) ? 1.f : nd;
    float X0 = d0/snd, X1 = d1/snd, X2 = d2/snd;
    float Za0 = RA[6]+RB[6], Za1 = RA[7]+RB[7], Za2 = RA[8]+RB[8];
    float Zs0 = RA[6]-RB[6], Zs1 = RA[7]-RB[7], Zs2 = RA[8]-RB[8];
    float na = sqrtf(Za0*Za0 + Za1*Za1 + Za2*Za2);
    float ns = sqrtf(Zs0*Zs0 + Zs1*Zs1 + Zs2*Zs2);
    float Z0, Z1, Z2;
    if (na > ns) { float s = (na == 0.f) ? 1.f : na; Z0 = Za0/s; Z1 = Za1/s; Z2 = Za2/s; }
    else         { float s = (ns == 0.f) ? 1.f : ns; Z0 = Zs0/s; Z1 = Zs1/s; Z2 = Zs2/s; }
    /* Y = Z x X */
    float Y0 = Z1*X2 - Z2*X1;
    float Y1 = Z2*X0 - Z0*X2;
    float Y2 = Z0*X1 - Z1*X0;
    bool nanbad = isnan(Y0) || isnan(Y1) || isnan(Y2);
    /* flip if dot(X x Y, Z) < 0 */
    float C0 = X1*Y2 - X2*Y1;
    float C1 = X2*Y0 - X0*Y2;
    float C2 = X0*Y1 - X1*Y0;
    if (C0*Z0 + C1*Z1 + C2*Z2 < 0.f) { Y0 = -Y0; Y1 = -Y1; Y2 = -Y2; }
    bool bad = close || (nd == 0.f) || (na == 0.f) || (ns == 0.f) || nanbad;
    if (bad) {
#pragma unroll
        for (int k = 0; k < 9; k++) R[k] = RA[k];
        O[0] = OA[0]; O[1] = OA[1]; O[2] = OA[2];
    } else {
        R[0] = X0; R[1] = X1; R[2] = X2;
        R[3] = Y0; R[4] = Y1; R[5] = Y2;
        R[6] = Z0; R[7] = Z1; R[8] = Z2;
        O[0] = 0.5f*(OA[0]+OB[0]); O[1] = 0.5f*(OA[1]+OB[1]); O[2] = 0.5f*(OA[2]+OB[2]);
    }
}

/* --------------- base frames: rigid_from_3(target) + record[0..L) -- */
__global__ void base_kernel(const float* __restrict__ rot, const float* __restrict__ trans,
                            const float* __restrict__ target, int L) {
    int l = blockIdx.x * blockDim.x + threadIdx.x;
    if (l >= L) return;
    float Rp[9], tp[3];
#pragma unroll
    for (int k = 0; k < 9; k++) Rp[k] = rot[(long)l*9 + k];
    tp[0] = trans[l*3+0]; tp[1] = trans[l*3+1]; tp[2] = trans[l*3+2];

    const float* x = target + (long)l*9;
    float x1x = x[0], x1y = x[1], x1z = x[2];
    float x2x = x[3], x2y = x[4], x2z = x[5];
    float x3x = x[6], x3y = x[7], x3z = x[8];
    float v1x = x3x - x2x, v1y = x3y - x2y, v1z = x3z - x2z;
    float v2x = x1x - x2x, v2y = x1y - x2y, v2z = x1z - x2z;
    float n1 = sqrtf(v1x*v1x + v1y*v1y + v1z*v1z) + 0.001f;
    float e1x = v1x/n1, e1y = v1y/n1, e1z = v1z/n1;
    float dp = e1x*v2x + e1y*v2y + e1z*v2z;
    float u2x = v2x - e1x*dp, u2y = v2y - e1y*dp, u2z = v2z - e1z*dp;
    float n2 = sqrtf(u2x*u2x + u2y*u2y + u2z*u2z) + 1e-8f;
    float e2x = u2x/n2, e2y = u2y/n2, e2z = u2z/n2;
    float e3x = e1y*e2z - e1z*e2y;
    float e3y = e1z*e2x - e1x*e2z;
    float e3z = e1x*e2y - e1y*e2x;
    float Rt[9] = {e1x,e1y,e1z, e2x,e2y,e2z, e3x,e3y,e3z};
    float tq[3] = {x2x, x2y, x2z};
#pragma unroll
    for (int k = 0; k < 9; k++) g_trot[(long)l*9 + k] = Rt[k];
    g_ttran[l*3+0] = tq[0]; g_ttran[l*3+1] = tq[1]; g_ttran[l*3+2] = tq[2];

    write_record(l, Rp, tp, Rt, tq);
}

/* --------------- merged frames for pairs → record[L..L+P) ---------- */
__global__ void merge_kernel(const float* __restrict__ rot, const float* __restrict__ trans, int L) {
    int p = blockIdx.x * blockDim.x + threadIdx.x;
    int P = min(g_pair_count, MAX_P);
    if (p >= P) return;
    int i = g_pairs[p].x, j = g_pairs[p].y;
    float Rp[9], tp[3], Rt[9], tq[3];
    merge_frames_dev(rot + (long)9*i, trans + (long)3*i,
                     rot + (long)9*j, trans + (long)3*j, Rp, tp);
    merge_frames_dev(g_trot + (long)9*i, g_ttran + (long)3*i,
                     g_trot + (long)9*j, g_ttran + (long)3*j, Rt, tq);
    write_record(L + p, Rp, tp, Rt, tq);
}

/* --------------- main: sum over (points x frames) ------------------ */
__global__ void __launch_bounds__(NT_MAIN, 2)
fape_main_kernel(const float* __restrict__ coor, const float* __restrict__ target, int L) {
    const int npts = 3 * L;
    const int t = threadIdx.x;

    /* per-thread points in registers; contiguous-in-k activity */
    int kact = (t < npts) ? ((npts - 1 - t) / NT_MAIN + 1) : 0;
    if (kact > MAX_PPT) kact = MAX_PPT;
    float px[MAX_PPT], py[MAX_PPT], pz[MAX_PPT];
    float qx[MAX_PPT], qy[MAX_PPT], qz[MAX_PPT];
#pragma unroll
    for (int k = 0; k < MAX_PPT; k++) {
        int n = t + k * NT_MAIN;
        int nn = (n < npts) ? n : 0;
        px[k] = coor[3*nn];   py[k] = coor[3*nn+1];   pz[k] = coor[3*nn+2];
        qx[k] = target[3*nn]; qy[k] = target[3*nn+1]; qz[k] = target[3*nn+2];
    }

    int F = L + min(g_pair_count, MAX_P);
    float acc = 0.f;

    for (int f = blockIdx.x; f < F; f += gridDim.x) {
        const float4* fr = g_frames4 + (long)f * 6;
        float4 a0 = fr[0], a1 = fr[1], a2 = fr[2], a3 = fr[3], a4 = fr[4], a5 = fr[5];
        float r00=a0.x, r01=a0.y, r02=a0.z, r10=a0.w;
        float r11=a1.x, r12=a1.y, r20=a1.z, r21=a1.w;
        float r22=a2.x;
        float s00=a2.y, s01=a2.z, s02=a2.w;
        float s10=a3.x, s11=a3.y, s12=a3.z, s20=a3.w;
        float s21=a4.x, s22=a4.y;
        float c0 =a4.z, c1 =a4.w, c2 =a5.x;
#pragma unroll
        for (int k = 0; k < MAX_PPT; k++) {
            if (k < kact) {
                float u0 = fmaf(r00, px[k], fmaf(r01, py[k], fmaf(r02, pz[k], c0)));
                float v0 = fmaf(s00, qx[k], fmaf(s01, qy[k], s02 * qz[k]));
                float d0 = u0 - v0;
                float u1 = fmaf(r10, px[k], fmaf(r11, py[k], fmaf(r12, pz[k], c1)));
                float v1 = fmaf(s10, qx[k], fmaf(s11, qy[k], s12 * qz[k]));
                float d1 = u1 - v1;
                float u2 = fmaf(r20, px[k], fmaf(r21, py[k], fmaf(r22, pz[k], c2)));
                float v2 = fmaf(s20, qx[k], fmaf(s21, qy[k], s22 * qz[k]));
                float d2 = u2 - v2;
                float ss = fmaf(d0, d0, fmaf(d1, d1, fmaf(d2, d2, EP3)));
                ss = fminf(ss, EPMAX2);           /* min(sqrt(s),30)==sqrt(min(s,900)) */
                float r;
                asm("sqrt.approx.f32 %0, %1;" : "=f"(r) : "f"(ss));
                acc += r;
            }
        }
    }

    /* block reduction → one double atomic per block */
#pragma unroll
    for (int off = 16; off; off >>= 1)
        acc += __shfl_down_sync(0xffffffffu, acc, off);
    __shared__ float wsum[NT_MAIN / 32];
    if ((t & 31) == 0) wsum[t >> 5] = acc;
    __syncthreads();
    if (t < NT_MAIN / 32) {
        float v = wsum[t];
#pragma unroll
        for (int off = NT_MAIN / 64; off; off >>= 1)
            v += __shfl_down_sync(0xffu, v, off, NT_MAIN / 32);
        if (t == 0) atomicAdd(&g_sum, (double)v);
    }
}

/* --------------- finalize ------------------------------------------ */
__global__ void finalize_kernel(float* out, int L) {
    long F = (long)L + (long)min(g_pair_count, MAX_P);
    double denom = (double)(3 * L) * (double)F;
    out[0] = (float)(g_sum / denom);
}

/* ------------------------------------------------------------------ */
extern "C" void kernel_launch(void* const* d_in, const int* in_sizes, int n_in,
                              void* d_out, int out_size) {
    const float* coor   = (const float*)d_in[0];
    const float* rot    = (const float*)d_in[1];
    const float* trans  = (const float*)d_in[2];
    const float* target = (const float*)d_in[3];
    const int*   matrix = (const int*)d_in[4];
    int L = in_sizes[0] / 9;

    init_kernel<<<1, 1>>>();
    dim3 pg(L, (L + 255) / 256);
    pairs_kernel<<<pg, 256>>>(matrix, L);
    base_kernel<<<(L + 127) / 128, 128>>>(rot, trans, target, L);
    merge_kernel<<<(MAX_P + 255) / 256, 256>>>(rot, trans, L);
    fape_main_kernel<<<NB_MAIN, NT_MAIN>>>(coor, target, L);
    finalize_kernel<<<1, 1>>>((float*)d_out, L);
}

// round 2
// speedup vs baseline: 1.1751x; 1.1751x over previous
#include <cuda_runtime.h>
#include <math.h>

#define FATOL 1e-8f
#define FRTOL 1e-5f
#define EP3   0.0003f      /* 3 * EP, EP = 1e-4 */
#define EPMAX2 900.0f      /* EPMAX^2 */

#define MAX_L 2048
#define MAX_P 131072
#define MAX_F (MAX_L + MAX_P)
#define NT_MAIN 512
#define NB_MAIN 152
#define NSLOT 3            /* 2 points per slot -> 6 points/thread, npts<=3072 */

typedef unsigned long long u64;

#define FMA2(d,a,b,c) asm("fma.rn.f32x2 %0, %1, %2, %3;" : "=l"(d) : "l"(a), "l"(b), "l"(c))
#define PACK2(d,lo,hi) asm("mov.b64 %0, {%1, %2};" : "=l"(d) : "f"(lo), "f"(hi))
#define UNPK2(lo,hi,s) asm("mov.b64 {%0, %1}, %2;" : "=f"(lo), "=f"(hi) : "l"(s))

struct Ctl { int pair_count; int done; double sum; };
__device__ Ctl    g_ctl;
__device__ int2   g_pairs[MAX_P];
__device__ float4 g_frames4[(long)MAX_F * 6];  /* per frame: Rp[9], -Rt[9], c[3], pad */
__device__ float  g_trot[MAX_L * 9];
__device__ float  g_ttran[MAX_L * 3];

/* ---------------- pair extraction ---------------------------------- */
__global__ void pairs_kernel_vec4(const int* __restrict__ m, int L) {
    int i  = blockIdx.x;
    int j4 = (blockIdx.y * blockDim.x + threadIdx.x) * 4;
    int cnt = 0; int js[4];
    if (j4 < L) {
        int4 v = *(const int4*)(m + (long)i * L + j4);
        int vv[4] = {v.x, v.y, v.z, v.w};
#pragma unroll
        for (int u = 0; u < 4; u++) {
            int j = j4 + u;
            if (j < L && j > i && vv[u] == 1) js[cnt++] = j;
        }
    }
    /* warp inclusive scan of cnt */
    int lane = threadIdx.x & 31;
    int scan = cnt;
#pragma unroll
    for (int off = 1; off < 32; off <<= 1) {
        int n = __shfl_up_sync(0xffffffffu, scan, off);
        if (lane >= off) scan += n;
    }
    int total = __shfl_sync(0xffffffffu, scan, 31);
    int base = 0;
    if (lane == 31 && total) base = atomicAdd(&g_ctl.pair_count, total);
    base = __shfl_sync(0xffffffffu, base, 31);
    int pos = base + scan - cnt;
    for (int u = 0; u < cnt; u++)
        if (pos + u < MAX_P) g_pairs[pos + u] = make_int2(i, js[u]);
}

__global__ void pairs_kernel_scalar(const int* __restrict__ m, int L) {
    int i = blockIdx.x;
    int j = blockIdx.y * blockDim.x + threadIdx.x;
    bool pred = (j < L) && (j > i) && (m[(long)i * L + j] == 1);
    unsigned bal = __ballot_sync(0xffffffffu, pred);
    int cnt = __popc(bal);
    int lane = threadIdx.x & 31;
    int base = 0;
    if (lane == 0 && cnt) base = atomicAdd(&g_ctl.pair_count, cnt);
    base = __shfl_sync(0xffffffffu, base, 0);
    if (pred) {
        int r = base + __popc(bal & ((1u << lane) - 1u));
        if (r < MAX_P) g_pairs[r] = make_int2(i, j);
    }
}

/* ---------------- frame record: Rp[9], -Rt[9], c[3] ---------------- */
__device__ __forceinline__ void write_record(int f, const float* Rp, const float* tp,
                                             const float* Rt, const float* tq) {
    float c[3];
#pragma unroll
    for (int e = 0; e < 3; e++)
        c[e] = (Rt[3*e+0]*tq[0] + Rt[3*e+1]*tq[1] + Rt[3*e+2]*tq[2])
             - (Rp[3*e+0]*tp[0] + Rp[3*e+1]*tp[1] + Rp[3*e+2]*tp[2]);
    float4* o = g_frames4 + (long)f * 6;
    o[0] = make_float4( Rp[0],  Rp[1],  Rp[2],  Rp[3]);
    o[1] = make_float4( Rp[4],  Rp[5],  Rp[6],  Rp[7]);
    o[2] = make_float4( Rp[8], -Rt[0], -Rt[1], -Rt[2]);
    o[3] = make_float4(-Rt[3], -Rt[4], -Rt[5], -Rt[6]);
    o[4] = make_float4(-Rt[7], -Rt[8],  c[0],   c[1]);
    o[5] = make_float4( c[2],   0.f,    0.f,    0.f);
}

__device__ __forceinline__ void merge_frames_dev(
    const float* RA, const float* OA, const float* RB, const float* OB,
    float* R, float* O)
{
    bool close = (fabsf(OA[0]-OB[0]) <= FATOL + FRTOL*fabsf(OB[0]))
              && (fabsf(OA[1]-OB[1]) <= FATOL + FRTOL*fabsf(OB[1]))
              && (fabsf(OA[2]-OB[2]) <= FATOL + FRTOL*fabsf(OB[2]));
    float d0 = OB[0]-OA[0], d1 = OB[1]-OA[1], d2 = OB[2]-OA[2];
    float nd = sqrtf(d0*d0 + d1*d1 + d2*d2);
    float snd = (nd == 0.f) ? 1.f : nd;
    float X0 = d0/snd, X1 = d1/snd, X2 = d2/snd;
    float Za0 = RA[6]+RB[6], Za1 = RA[7]+RB[7], Za2 = RA[8]+RB[8];
    float Zs0 = RA[6]-RB[6], Zs1 = RA[7]-RB[7], Zs2 = RA[8]-RB[8];
    float na = sqrtf(Za0*Za0 + Za1*Za1 + Za2*Za2);
    float ns = sqrtf(Zs0*Zs0 + Zs1*Zs1 + Zs2*Zs2);
    float Z0, Z1, Z2;
    if (na > ns) { float s = (na == 0.f) ? 1.f : na; Z0 = Za0/s; Z1 = Za1/s; Z2 = Za2/s; }
    else         { float s = (ns == 0.f) ? 1.f : ns; Z0 = Zs0/s; Z1 = Zs1/s; Z2 = Zs2/s; }
    float Y0 = Z1*X2 - Z2*X1;
    float Y1 = Z2*X0 - Z0*X2;
    float Y2 = Z0*X1 - Z1*X0;
    bool nanbad = isnan(Y0) || isnan(Y1) || isnan(Y2);
    float C0 = X1*Y2 - X2*Y1;
    float C1 = X2*Y0 - X0*Y2;
    float C2 = X0*Y1 - X1*Y0;
    if (C0*Z0 + C1*Z1 + C2*Z2 < 0.f) { Y0 = -Y0; Y1 = -Y1; Y2 = -Y2; }
    bool bad = close || (nd == 0.f) || (na == 0.f) || (ns == 0.f) || nanbad;
    if (bad) {
#pragma unroll
        for (int k = 0; k < 9; k++) R[k] = RA[k];
        O[0] = OA[0]; O[1] = OA[1]; O[2] = OA[2];
    } else {
        R[0] = X0; R[1] = X1; R[2] = X2;
        R[3] = Y0; R[4] = Y1; R[5] = Y2;
        R[6] = Z0; R[7] = Z1; R[8] = Z2;
        O[0] = 0.5f*(OA[0]+OB[0]); O[1] = 0.5f*(OA[1]+OB[1]); O[2] = 0.5f*(OA[2]+OB[2]);
    }
}

/* --------------- base frames -------------------------------------- */
__global__ void base_kernel(const float* __restrict__ rot, const float* __restrict__ trans,
                            const float* __restrict__ target, int L) {
    int l = blockIdx.x * blockDim.x + threadIdx.x;
    if (l >= L) return;
    float Rp[9], tp[3];
#pragma unroll
    for (int k = 0; k < 9; k++) Rp[k] = rot[(long)l*9 + k];
    tp[0] = trans[l*3+0]; tp[1] = trans[l*3+1]; tp[2] = trans[l*3+2];

    const float* x = target + (long)l*9;
    float x1x = x[0], x1y = x[1], x1z = x[2];
    float x2x = x[3], x2y = x[4], x2z = x[5];
    float x3x = x[6], x3y = x[7], x3z = x[8];
    float v1x = x3x - x2x, v1y = x3y - x2y, v1z = x3z - x2z;
    float v2x = x1x - x2x, v2y = x1y - x2y, v2z = x1z - x2z;
    float n1 = sqrtf(v1x*v1x + v1y*v1y + v1z*v1z) + 0.001f;
    float e1x = v1x/n1, e1y = v1y/n1, e1z = v1z/n1;
    float dp = e1x*v2x + e1y*v2y + e1z*v2z;
    float u2x = v2x - e1x*dp, u2y = v2y - e1y*dp, u2z = v2z - e1z*dp;
    float n2 = sqrtf(u2x*u2x + u2y*u2y + u2z*u2z) + 1e-8f;
    float e2x = u2x/n2, e2y = u2y/n2, e2z = u2z/n2;
    float e3x = e1y*e2z - e1z*e2y;
    float e3y = e1z*e2x - e1x*e2z;
    float e3z = e1x*e2y - e1y*e2x;
    float Rt[9] = {e1x,e1y,e1z, e2x,e2y,e2z, e3x,e3y,e3z};
    float tq[3] = {x2x, x2y, x2z};
#pragma unroll
    for (int k = 0; k < 9; k++) g_trot[(long)l*9 + k] = Rt[k];
    g_ttran[l*3+0] = tq[0]; g_ttran[l*3+1] = tq[1]; g_ttran[l*3+2] = tq[2];

    write_record(l, Rp, tp, Rt, tq);
}

/* --------------- merged pair frames (grid-stride) ------------------ */
__global__ void merge_kernel(const float* __restrict__ rot, const float* __restrict__ trans, int L) {
    int P = min(g_ctl.pair_count, MAX_P);
    for (int p = blockIdx.x * blockDim.x + threadIdx.x; p < P; p += gridDim.x * blockDim.x) {
        int i = g_pairs[p].x, j = g_pairs[p].y;
        float Rp[9], tp[3], Rt[9], tq[3];
        merge_frames_dev(rot + (long)9*i, trans + (long)3*i,
                         rot + (long)9*j, trans + (long)3*j, Rp, tp);
        merge_frames_dev(g_trot + (long)9*i, g_ttran + (long)3*i,
                         g_trot + (long)9*j, g_ttran + (long)3*j, Rt, tq);
        write_record(L + p, Rp, tp, Rt, tq);
    }
}

/* --------------- main: f32x2 packed point x frame sum -------------- */
template<bool FULL>
__global__ void __launch_bounds__(NT_MAIN, 1)
fape_main_kernel(const float* __restrict__ coor, const float* __restrict__ target,
                 int L, float* __restrict__ out) {
    const int npts = 3 * L;
    const int t = threadIdx.x;

    u64 Px[NSLOT], Py[NSLOT], Pz[NSLOT], Qx[NSLOT], Qy[NSLOT], Qz[NSLOT];
    float M0[NSLOT], M1[NSLOT];
#pragma unroll
    for (int k = 0; k < NSLOT; k++) {
        int n0 = t + (2*k)   * NT_MAIN;
        int n1 = t + (2*k+1) * NT_MAIN;
        int a0 = (n0 < npts) ? n0 : 0;
        int a1 = (n1 < npts) ? n1 : 0;
        float p0x = coor[3*a0],   p0y = coor[3*a0+1],   p0z = coor[3*a0+2];
        float p1x = coor[3*a1],   p1y = coor[3*a1+1],   p1z = coor[3*a1+2];
        float q0x = target[3*a0], q0y = target[3*a0+1], q0z = target[3*a0+2];
        float q1x = target[3*a1], q1y = target[3*a1+1], q1z = target[3*a1+2];
        PACK2(Px[k], p0x, p1x); PACK2(Py[k], p0y, p1y); PACK2(Pz[k], p0z, p1z);
        PACK2(Qx[k], q0x, q1x); PACK2(Qy[k], q0y, q1y); PACK2(Qz[k], q0z, q1z);
        if (!FULL) {
            M0[k] = (n0 < npts) ? 1.f : 0.f;
            M1[k] = (n1 < npts) ? 1.f : 0.f;
        }
    }

    int F = L + min(g_ctl.pair_count, MAX_P);
    float acc0 = 0.f, acc1 = 0.f;

    for (int f = blockIdx.x; f < F; f += gridDim.x) {
        const float4* fr = g_frames4 + (long)f * 6;
        float4 a0 = fr[0], a1 = fr[1], a2 = fr[2], a3 = fr[3], a4 = fr[4], a5 = fr[5];
        u64 R00,R01,R02,R10,R11,R12,R20,R21,R22;
        u64 S00,S01,S02,S10,S11,S12,S20,S21,S22;
        u64 C0,C1,C2;
        PACK2(R00,a0.x,a0.x); PACK2(R01,a0.y,a0.y); PACK2(R02,a0.z,a0.z);
        PACK2(R10,a0.w,a0.w); PACK2(R11,a1.x,a1.x); PACK2(R12,a1.y,a1.y);
        PACK2(R20,a1.z,a1.z); PACK2(R21,a1.w,a1.w); PACK2(R22,a2.x,a2.x);
        PACK2(S00,a2.y,a2.y); PACK2(S01,a2.z,a2.z); PACK2(S02,a2.w,a2.w);
        PACK2(S10,a3.x,a3.x); PACK2(S11,a3.y,a3.y); PACK2(S12,a3.z,a3.z);
        PACK2(S20,a3.w,a3.w); PACK2(S21,a4.x,a4.x); PACK2(S22,a4.y,a4.y);
        PACK2(C0, a4.z,a4.z); PACK2(C1, a4.w,a4.w); PACK2(C2, a5.x,a5.x);
        u64 EPp; PACK2(EPp, EP3, EP3);

#pragma unroll
        for (int k = 0; k < NSLOT; k++) {
            u64 d0, d1, d2, ss;
            FMA2(d0, S02, Qz[k], C0);  FMA2(d0, S01, Qy[k], d0); FMA2(d0, S00, Qx[k], d0);
            FMA2(d0, R02, Pz[k], d0);  FMA2(d0, R01, Py[k], d0); FMA2(d0, R00, Px[k], d0);
            FMA2(d1, S12, Qz[k], C1);  FMA2(d1, S11, Qy[k], d1); FMA2(d1, S10, Qx[k], d1);
            FMA2(d1, R12, Pz[k], d1);  FMA2(d1, R11, Py[k], d1); FMA2(d1, R10, Px[k], d1);
            FMA2(d2, S22, Qz[k], C2);  FMA2(d2, S21, Qy[k], d2); FMA2(d2, S20, Qx[k], d2);
            FMA2(d2, R22, Pz[k], d2);  FMA2(d2, R21, Py[k], d2); FMA2(d2, R20, Px[k], d2);
            FMA2(ss, d2, d2, EPp); FMA2(ss, d1, d1, ss); FMA2(ss, d0, d0, ss);
            float s0, s1; UNPK2(s0, s1, ss);
            s0 = fminf(s0, EPMAX2);  s1 = fminf(s1, EPMAX2);
            float r0, r1;
            asm("sqrt.approx.f32 %0, %1;" : "=f"(r0) : "f"(s0));
            asm("sqrt.approx.f32 %0, %1;" : "=f"(r1) : "f"(s1));
            if (FULL) { acc0 += r0; acc1 += r1; }
            else      { acc0 = fmaf(M0[k], r0, acc0); acc1 = fmaf(M1[k], r1, acc1); }
        }
    }

    /* block reduction -> one double atomic, last block finalizes */
    float acc = acc0 + acc1;
#pragma unroll
    for (int off = 16; off; off >>= 1)
        acc += __shfl_down_sync(0xffffffffu, acc, off);
    __shared__ float wsum[NT_MAIN / 32];
    if ((t & 31) == 0) wsum[t >> 5] = acc;
    __syncthreads();
    if (t == 0) {
        float v = 0.f;
#pragma unroll
        for (int w = 0; w < NT_MAIN / 32; w++) v += wsum[w];
        atomicAdd(&g_ctl.sum, (double)v);
        __threadfence();
        int d = atomicAdd(&g_ctl.done, 1);
        if (d == gridDim.x - 1) {
            double s = atomicAdd(&g_ctl.sum, 0.0);
            out[0] = (float)(s / ((double)npts * (double)F));
        }
    }
}

/* ------------------------------------------------------------------ */
extern "C" void kernel_launch(void* const* d_in, const int* in_sizes, int n_in,
                              void* d_out, int out_size) {
    const float* coor   = (const float*)d_in[0];
    const float* rot    = (const float*)d_in[1];
    const float* trans  = (const float*)d_in[2];
    const float* target = (const float*)d_in[3];
    const int*   matrix = (const int*)d_in[4];
    int L = in_sizes[0] / 9;
    int npts = 3 * L;

    void* ctl_ptr = nullptr;
    cudaGetSymbolAddress(&ctl_ptr, g_ctl);
    cudaMemsetAsync(ctl_ptr, 0, sizeof(Ctl));

    if (L % 4 == 0) {
        dim3 pg(L, (L + 1023) / 1024);
        pairs_kernel_vec4<<<pg, 256>>>(matrix, L);
    } else {
        dim3 pg(L, (L + 255) / 256);
        pairs_kernel_scalar<<<pg, 256>>>(matrix, L);
    }
    base_kernel<<<(L + 127) / 128, 128>>>(rot, trans, target, L);
    merge_kernel<<<96, 128>>>(rot, trans, L);

    if (npts == NT_MAIN * 2 * NSLOT)
        fape_main_kernel<true ><<<NB_MAIN, NT_MAIN>>>(coor, target, L, (float*)d_out);
    else
        fape_main_kernel<false><<<NB_MAIN, NT_MAIN>>>(coor, target, L, (float*)d_out);
}